// round 15
// baseline (speedup 1.0000x reference)
#include <cuda_runtime.h>
#include <cuda_fp16.h>
#include <cstdint>

// ---------------------------------------------------------------------------
// Problem constants
// ---------------------------------------------------------------------------
static constexpr int IN_F   = 512;
static constexpr int OUT_F  = 512;
static constexpr int NEXP   = 8;
static constexpr int NGRP   = 32;
static constexpr int TPG    = 2048;

// Static device scratch.
// g_xt: A tiles, pre-swizzled fp16. tile id ((g*16+mtile)*8+kc), 16 KB each.
// g_wt: B tiles, pre-swizzled fp16. tile id ((g*4+ntile)*8+kc), 16 KB each.
__device__ unsigned char g_xt[(size_t)4096 * 16384];    // 67 MB
__device__ unsigned char g_wt[(size_t)1024 * 16384];    // 16.8 MB
__device__ float g_b[NGRP * OUT_F];

// Data-flow gating state (reset by zero_kernel every run).
__device__ int g_flagA[4096];    // one per A tile
__device__ int g_wcnt;           // mixW + mixB completion counter (target 1088)

// ---------------------------------------------------------------------------
// Helpers
// ---------------------------------------------------------------------------
__device__ __forceinline__ uint32_t smem_u32(const void* p) {
    uint32_t a;
    asm("{ .reg .u64 t; cvta.to.shared.u64 t, %1; cvt.u32.u64 %0, t; }"
        : "=r"(a) : "l"(p));
    return a;
}

__device__ __forceinline__ uint32_t sw128(uint32_t o) {
    return o ^ ((o >> 3) & 0x70);
}

__device__ __forceinline__ void ldsm4(uint32_t r[4], uint32_t addr) {
    asm volatile("ldmatrix.sync.aligned.m8n8.x4.shared.b16 {%0,%1,%2,%3}, [%4];"
                 : "=r"(r[0]), "=r"(r[1]), "=r"(r[2]), "=r"(r[3]) : "r"(addr));
}

__device__ __forceinline__ void mma16816(float c[4], const uint32_t a[4],
                                         uint32_t b0, uint32_t b1) {
    asm volatile(
        "mma.sync.aligned.m16n8k16.row.col.f32.f16.f16.f32 "
        "{%0,%1,%2,%3}, {%4,%5,%6,%7}, {%8,%9}, {%0,%1,%2,%3};"
        : "+f"(c[0]), "+f"(c[1]), "+f"(c[2]), "+f"(c[3])
        : "r"(a[0]), "r"(a[1]), "r"(a[2]), "r"(a[3]), "r"(b0), "r"(b1));
}

__device__ __forceinline__ int ld_acquire(const int* p) {
    int v;
    asm volatile("ld.global.acquire.gpu.b32 %0, [%1];" : "=r"(v) : "l"(p) : "memory");
    return v;
}

__device__ __forceinline__ void st_release(int* p, int v) {
    asm volatile("st.global.release.gpu.b32 [%0], %1;" :: "l"(p), "r"(v) : "memory");
}

#define MBARRIER_INIT(mbar, count) \
    asm volatile("mbarrier.init.shared.b64 [%0], %1;" \
        :: "r"((uint32_t)(mbar)), "r"((uint32_t)(count)) : "memory")

#define MBARRIER_ARRIVE(mbar) \
    asm volatile("mbarrier.arrive.shared.b64 _, [%0];" \
        :: "r"((uint32_t)(mbar)) : "memory")

#define MBARRIER_EXPECT_TX(mbar, tx) \
    asm volatile("mbarrier.arrive.expect_tx.shared.b64 _, [%0], %1;" \
        :: "r"((uint32_t)(mbar)), "r"((uint32_t)(tx)) : "memory")

#define MBARRIER_WAIT_PARITY(mbar_smem_addr, phase_parity) do {                        \
    uint32_t _mbar = (uint32_t)(mbar_smem_addr);                                       \
    uint32_t _parity = (uint32_t)(phase_parity);                                       \
    uint32_t _done;                                                                    \
    asm volatile(                                                                      \
        "{\n\t.reg .pred p;\n\t"                                                       \
        "mbarrier.try_wait.parity.acquire.cta.shared::cta.b64 p, [%1], %2;\n\t"        \
        "selp.b32 %0, 1, 0, p;\n\t}"                                                   \
        : "=r"(_done) : "r"(_mbar), "r"(_parity) : "memory");                          \
    if (!_done) {                                                                      \
        asm volatile(                                                                  \
            "{\n\t.reg .pred P1;\n\t"                                                  \
            "WAIT_LOOP_%=:\n\t"                                                        \
            "mbarrier.try_wait.parity.acquire.cta.shared::cta.b64 P1, [%0], %1, 0x989680;\n\t" \
            "@P1 bra.uni WAIT_DONE_%=;\n\t"                                            \
            "bra.uni WAIT_LOOP_%=;\n\t"                                                \
            "WAIT_DONE_%=:\n\t}"                                                       \
            :: "r"(_mbar), "r"(_parity) : "memory");                                   \
    }                                                                                  \
} while (0)

// 1D bulk async copy gmem -> smem with mbarrier transaction completion.
#define CP_BULK(dstS, srcG, nbytes, mbar) \
    asm volatile( \
        "cp.async.bulk.shared::cluster.global.mbarrier::complete_tx::bytes " \
        "[%0], [%1], %2, [%3];" \
        :: "r"((uint32_t)(dstS)), "l"(srcG), "r"((uint32_t)(nbytes)), \
           "r"((uint32_t)(mbar)) : "memory")

// ---------------------------------------------------------------------------
// Kernel 0: reset gating state
// ---------------------------------------------------------------------------
__global__ void __launch_bounds__(256) zero_kernel() {
    int i = blockIdx.x * 256 + threadIdx.x;
    if (i < 4096) g_flagA[i] = 0;
    if (i == 0) g_wcnt = 0;
}

// ---------------------------------------------------------------------------
// Mega kernel: block roles by blockIdx.x
//   [0, 1024):     mix expert weights -> pre-swizzled fp16 B tiles (g_wt)
//   [1024, 1088):  mix bias -> g_b
//   [1088, 7232):  per-group interleave: for each g: 128 cvtA blocks then
//                  64 GEMM blocks. GEMM gates on g_wcnt and per-A-tile flags.
// ---------------------------------------------------------------------------
static constexpr int MIXW_BLKS = (OUT_F * IN_F) / 256;     // 1024
static constexpr int MIXB_BLKS = (NGRP * OUT_F) / 256;     // 64
static constexpr int WCNT_TARGET = MIXW_BLKS + MIXB_BLKS;  // 1088
static constexpr int GRID_TOTAL = WCNT_TARGET + NGRP * (128 + 64);   // 7232

// GEMM smem layout (dynamic): CTA tile M=128, N=128, K-chunk=64.
static constexpr int OFF_BIAS  = 0;                      // 128 f32 = 512 B
static constexpr int OFF_FULL  = 512;                    // 3 x 8 B
static constexpr int OFF_EMPTY = 512 + 24;               // 3 x 8 B
static constexpr int OFF_STAGE = 1024;
static constexpr int STAGE_SZ  = 16384 + 16384;          // A 16KB + B 16KB
static constexpr int SMEM_TOTAL = OFF_STAGE + 3 * STAGE_SZ;   // 99328

__device__ __forceinline__ uint32_t stageA(uint32_t sb, int s) {
    return sb + OFF_STAGE + s * STAGE_SZ;
}
__device__ __forceinline__ uint32_t stageB(uint32_t sb, int s) {
    return sb + OFF_STAGE + s * STAGE_SZ + 16384;
}

__device__ __forceinline__ void compute_chunk(uint32_t aBase, uint32_t bBase,
                                              int wm, int wn, int lane,
                                              float acc[2][8][4]) {
#pragma unroll
    for (int kk = 0; kk < 4; kk++) {
        int c0 = kk * 2;
        uint32_t a[2][4];
#pragma unroll
        for (int mt = 0; mt < 2; mt++) {
            int r = wm * 32 + mt * 16 + (lane & 15);
            int c = c0 + (lane >> 4);
            ldsm4(a[mt], aBase + sw128((uint32_t)(r * 128 + c * 16)));
        }
        uint32_t bb[4][4];
#pragma unroll
        for (int nt = 0; nt < 4; nt++) {
            int r = wn * 64 + nt * 16 + (lane & 7) + ((lane & 16) ? 8 : 0);
            int c = c0 + ((lane >> 3) & 1);
            ldsm4(bb[nt], bBase + sw128((uint32_t)(r * 128 + c * 16)));
        }
#pragma unroll
        for (int mt = 0; mt < 2; mt++)
#pragma unroll
            for (int nt = 0; nt < 4; nt++) {
                mma16816(acc[mt][nt * 2 + 0], a[mt], bb[nt][0], bb[nt][1]);
                mma16816(acc[mt][nt * 2 + 1], a[mt], bb[nt][2], bb[nt][3]);
            }
    }
}

__global__ void __launch_bounds__(256, 2) mole_fused(const float* __restrict__ x,
                                                     const float* __restrict__ coeff,
                                                     const float* __restrict__ we,
                                                     const float* __restrict__ be,
                                                     const float* __restrict__ ws,
                                                     const float* __restrict__ bs,
                                                     float* __restrict__ out) {
    extern __shared__ char smem[];
    int b = blockIdx.x;
    int tid = threadIdx.x;

    if (b < MIXW_BLKS) {
        // ---------------- mix expert weights into 16 KB B tiles ----------------
        float* sc = reinterpret_cast<float*>(smem);          // 256 floats
        sc[tid] = coeff[tid];                 // 256 == 32*8
        __syncthreads();
        int idx = b * 256 + tid;              // (o, i) flat
        int o = idx >> 9, i = idx & 511;
        float w[NEXP];
#pragma unroll
        for (int e = 0; e < NEXP; e++) w[e] = we[(size_t)e * OUT_F * IN_F + idx];
        float shared_w = ws[idx];
        uint32_t woff = sw128((uint32_t)((o & 127) * 128 + (i & 63) * 2));
        int tile_in_g = (o >> 7) * 8 + (i >> 6);     // ntile*8 + kc
#pragma unroll 4
        for (int g = 0; g < NGRP; g++) {
            float acc = shared_w;
#pragma unroll
            for (int e = 0; e < NEXP; e++) acc = fmaf(sc[g * NEXP + e], w[e], acc);
            size_t tile = (size_t)(g * 32 + tile_in_g) * 16384;
            *reinterpret_cast<__half*>(g_wt + tile + woff) = __float2half_rn(acc);
        }
        __syncthreads();
        __threadfence();
        if (tid == 0) atomicAdd(&g_wcnt, 1);
        return;
    }
    if (b < WCNT_TARGET) {
        // ---------------- mix bias ----------------
        int idx = (b - MIXW_BLKS) * 256 + tid;
        int g = idx >> 9, o = idx & 511;
        float acc = bs[o];
#pragma unroll
        for (int e = 0; e < NEXP; e++)
            acc = fmaf(coeff[g * NEXP + e], be[e * OUT_F + o], acc);
        g_b[idx] = acc;
        __syncthreads();
        __threadfence();
        if (tid == 0) atomicAdd(&g_wcnt, 1);
        return;
    }

    int r = b - WCNT_TARGET;
    int g = r / 192;
    int q = r % 192;

    if (q < 128) {
        // ---------------- cvt: one 16 KB A tile (g, mtile=q>>3, kc=q&7) ----------
        int t = g * 128 + q;
        int m_base = g * TPG + ((q >> 3) & 15) * 128;
        int kb = (q & 7) * 64;
        unsigned char* tile = g_xt + (size_t)t * 16384;
#pragma unroll
        for (int it = 0; it < 4; it++) {
            int u = tid + it * 256;          // 0..1023 (row, 16B unit)
            int row = u >> 3, c16 = u & 7;
            const float4* src = reinterpret_cast<const float4*>(
                x + (size_t)(m_base + row) * IN_F + kb + c16 * 8);
            float4 f0 = src[0], f1 = src[1];
            __half2 h0 = __floats2half2_rn(f0.x, f0.y);
            __half2 h1 = __floats2half2_rn(f0.z, f0.w);
            __half2 h2 = __floats2half2_rn(f1.x, f1.y);
            __half2 h3 = __floats2half2_rn(f1.z, f1.w);
            uint4 v;
            v.x = *reinterpret_cast<uint32_t*>(&h0);
            v.y = *reinterpret_cast<uint32_t*>(&h1);
            v.z = *reinterpret_cast<uint32_t*>(&h2);
            v.w = *reinterpret_cast<uint32_t*>(&h3);
            *reinterpret_cast<uint4*>(tile + sw128((uint32_t)(row * 128 + c16 * 16))) = v;
        }
        __syncthreads();
        __threadfence();
        if (tid == 0) st_release(&g_flagA[t], 1);
        return;
    }

    // ---------------- GEMM tile: (g, mtile, ntile) ----------------
    {
        int idx = q - 128;                   // 0..63
        int ntile = idx & 3;
        int mtile = idx >> 2;
        uint32_t sb = smem_u32(smem);
        int wid = tid >> 5, lane = tid & 31;
        int wm = wid & 3, wn = wid >> 2;      // warp grid 4(m) x 2(n)

        int m_base = g * TPG + mtile * 128;
        int n_base = ntile * 128;
        int aTileBase = g * 128 + mtile * 8;  // flag indices / tile ids
        const unsigned char* aTiles = g_xt + (size_t)aTileBase * 16384;
        const unsigned char* bTiles = g_wt + (size_t)((g * 4 + ntile) * 8) * 16384;

        if (tid == 0) {
            // gate on weight-mix completion (B tiles + bias ready)
            while (ld_acquire(&g_wcnt) < WCNT_TARGET) __nanosleep(256);
#pragma unroll
            for (int s = 0; s < 3; s++) {
                MBARRIER_INIT(sb + OFF_FULL + s * 8, 1);    // tx-tracked
                MBARRIER_INIT(sb + OFF_EMPTY + s * 8, 8);   // one arrive per warp
            }
        }
        __syncthreads();

        float* sbias = reinterpret_cast<float*>(smem + OFF_BIAS);
        if (tid < 128) sbias[tid] = g_b[g * OUT_F + n_base + tid];

        // prologue: chunks 0..2 into stages 0..2 (gated on A-tile flags)
        if (tid == 0) {
#pragma unroll
            for (int k = 0; k < 3; k++) {
                while (ld_acquire(&g_flagA[aTileBase + k]) == 0) __nanosleep(128);
                uint32_t mb = sb + OFF_FULL + k * 8;
                MBARRIER_EXPECT_TX(mb, STAGE_SZ);
                CP_BULK(stageA(sb, k), aTiles + (size_t)k * 16384, 16384, mb);
                CP_BULK(stageB(sb, k), bTiles + (size_t)k * 16384, 16384, mb);
            }
        }
        __syncthreads();   // sbias written before mainloop; epilogue reads it

        float acc[2][8][4];
#pragma unroll
        for (int i = 0; i < 2; i++)
#pragma unroll
            for (int j = 0; j < 8; j++)
#pragma unroll
                for (int l = 0; l < 4; l++) acc[i][j][l] = 0.0f;

#pragma unroll 1
        for (int k = 0; k < 8; k++) {
            int s = k % 3;
            int ph = (k / 3) & 1;
            MBARRIER_WAIT_PARITY(sb + OFF_FULL + s * 8, ph);
            compute_chunk(stageA(sb, s), stageB(sb, s), wm, wn, lane, acc);
            // ldmatrix is warp-synchronous: all lanes' reads of stage s done.
            if (lane == 0) MBARRIER_ARRIVE(sb + OFF_EMPTY + s * 8);
            if (k + 3 < 8 && tid == 0) {
                while (ld_acquire(&g_flagA[aTileBase + k + 3]) == 0) __nanosleep(128);
                MBARRIER_WAIT_PARITY(sb + OFF_EMPTY + s * 8, ph);
                uint32_t mb = sb + OFF_FULL + s * 8;
                MBARRIER_EXPECT_TX(mb, STAGE_SZ);
                CP_BULK(stageA(sb, s), aTiles + (size_t)(k + 3) * 16384, 16384, mb);
                CP_BULK(stageB(sb, s), bTiles + (size_t)(k + 3) * 16384, 16384, mb);
            }
        }

        // epilogue: direct fragment stores + bias
#pragma unroll
        for (int mt = 0; mt < 2; mt++) {
            int r0 = m_base + wm * 32 + mt * 16 + (lane >> 2);
#pragma unroll
            for (int nt8 = 0; nt8 < 8; nt8++) {
                int cl = wn * 64 + nt8 * 8 + (lane & 3) * 2;
                float bx = sbias[cl], by = sbias[cl + 1];
                float2 v0 = make_float2(acc[mt][nt8][0] + bx, acc[mt][nt8][1] + by);
                float2 v1 = make_float2(acc[mt][nt8][2] + bx, acc[mt][nt8][3] + by);
                *reinterpret_cast<float2*>(out + (size_t)r0 * OUT_F + n_base + cl) = v0;
                *reinterpret_cast<float2*>(out + (size_t)(r0 + 8) * OUT_F + n_base + cl) = v1;
            }
        }
    }
}

// ---------------------------------------------------------------------------
// launch
// ---------------------------------------------------------------------------
extern "C" void kernel_launch(void* const* d_in, const int* in_sizes, int n_in,
                              void* d_out, int out_size) {
    const float* x  = (const float*)d_in[0];
    const float* co = (const float*)d_in[1];
    const float* we = (const float*)d_in[2];
    const float* be = (const float*)d_in[3];
    const float* ws = (const float*)d_in[4];
    const float* bs = (const float*)d_in[5];
    float* out = (float*)d_out;

    cudaFuncSetAttribute(mole_fused, cudaFuncAttributeMaxDynamicSharedMemorySize,
                         SMEM_TOTAL);

    zero_kernel<<<16, 256>>>();
    mole_fused<<<GRID_TOTAL, 256, SMEM_TOTAL>>>(x, co, we, be, ws, bs, out);
}